// round 2
// baseline (speedup 1.0000x reference)
#include <cuda_runtime.h>
#include <cuda_bf16.h>

#define D 128
#define DV 32   // float4 per row

// Combined-table rows
#define R_T1 46           // atom (+bias)
#define R_T2 90           // deg(6) x h(5) x hyb(3)
#define R_T3 44           // chg(11) x chi(4)
#define R_B0 25           // (c0,c1)
#define R_B1 25           // (c2,c3)

#define OFF_T1 0
#define OFF_T2 (OFF_T1 + R_T1 * D)
#define OFF_T3 (OFF_T2 + R_T2 * D)
#define OFF_B0 (OFF_T3 + R_T3 * D)
#define OFF_B1 (OFF_B0 + R_B0 * D)
#define SMEM_FLOATS (OFF_B1 + R_B1 * D)          // 230*128 = 29440 floats
#define SMEM_BYTES  (SMEM_FLOATS * 4)            // 117760 B

#define NTHREADS 512

__device__ __forceinline__ void add4(float4& a, const float4 b) {
    a.x += b.x; a.y += b.y; a.z += b.z; a.w += b.w;
}
__device__ __forceinline__ void fma4(float4& a, float s, const float4 b) {
    a.x = fmaf(s, b.x, a.x); a.y = fmaf(s, b.y, a.y);
    a.z = fmaf(s, b.z, a.z); a.w = fmaf(s, b.w, a.w);
}

__global__ void __launch_bounds__(NTHREADS)
atom_featurizer_kernel(
    const int* __restrict__ atom_idx,
    const int* __restrict__ degree_idx,
    const int* __restrict__ charge_idx,
    const int* __restrict__ hybrid_idx,
    const int* __restrict__ numh_idx,
    const int* __restrict__ chiral_idx,
    const int* __restrict__ bond_counts,   // [N,4]
    const float* __restrict__ scalar3,     // [N,3]
    const float* __restrict__ E_atom,
    const float* __restrict__ E_deg,
    const float* __restrict__ E_chg,
    const float* __restrict__ E_hyb,
    const float* __restrict__ E_h,
    const float* __restrict__ E_chi,
    const float* __restrict__ E_bond,
    const float* __restrict__ Wm,
    const float* __restrict__ bv,
    float* __restrict__ out,
    int n)
{
    extern __shared__ float s[];
    const int t = threadIdx.x;

    // ---- Build combined tables (once per CTA; amortized over ~6.6k atoms) ----
    // T1[a] = E_atom[a] + b
    for (int e = t; e < R_T1 * D; e += NTHREADS)
        s[OFF_T1 + e] = E_atom[e] + bv[e & (D - 1)];
    // T2[(di*5+ni)*3+hi] = E_deg[di] + E_h[ni] + E_hyb[hi]
    for (int e = t; e < R_T2 * D; e += NTHREADS) {
        int row = e >> 7, col = e & (D - 1);
        int di = row / 15, rem = row % 15;
        int ni = rem / 3,  hi = rem % 3;
        s[OFF_T2 + e] = E_deg[di * D + col] + E_h[ni * D + col] + E_hyb[hi * D + col];
    }
    // T3[ci*4+xi] = E_chg[ci] + E_chi[xi]
    for (int e = t; e < R_T3 * D; e += NTHREADS) {
        int row = e >> 7, col = e & (D - 1);
        int ci = row >> 2, xi = row & 3;
        s[OFF_T3 + e] = E_chg[ci * D + col] + E_chi[xi * D + col];
    }
    // TB0[c0*5+c1] = m(c0)*E_bond[c0] + m(c1)*E_bond[c1] + 0.25*(c0*W3 + c1*W4)
    for (int e = t; e < R_B0 * D; e += NTHREADS) {
        int row = e >> 7, col = e & (D - 1);
        int c0 = row / 5, c1 = row % 5;
        float v = 0.25f * (c0 * Wm[3 * D + col] + c1 * Wm[4 * D + col]);
        if (c0 > 0) v += E_bond[c0 * D + col];
        if (c1 > 0) v += E_bond[c1 * D + col];
        s[OFF_B0 + e] = v;
    }
    // TB1[c2*5+c3] = m(c2)*E_bond[c2] + m(c3)*E_bond[c3] + 0.25*(c2*W5 + c3*W6)
    for (int e = t; e < R_B1 * D; e += NTHREADS) {
        int row = e >> 7, col = e & (D - 1);
        int c2 = row / 5, c3 = row % 5;
        float v = 0.25f * (c2 * Wm[5 * D + col] + c3 * Wm[6 * D + col]);
        if (c2 > 0) v += E_bond[c2 * D + col];
        if (c3 > 0) v += E_bond[c3 * D + col];
        s[OFF_B1 + e] = v;
    }

    const int lane = t & 31;
    // W rows 0..2: each lane's float4 slice is invariant -> registers
    const float4* W4 = reinterpret_cast<const float4*>(Wm);
    const float4 w0 = W4[0 * DV + lane];
    const float4 w1 = W4[1 * DV + lane];
    const float4 w2 = W4[2 * DV + lane];

    __syncthreads();

    const float4* s4 = reinterpret_cast<const float4*>(s);
    const int warp_global = (blockIdx.x * NTHREADS + t) >> 5;
    const int nwarps = (gridDim.x * NTHREADS) >> 5;
    float4* out4 = reinterpret_cast<float4*>(out);

    for (int i = warp_global; i < n; i += nwarps) {
        // per-atom metadata (uniform across the warp -> broadcast loads)
        const int ai = atom_idx[i];
        const int di = degree_idx[i];
        const int ci = charge_idx[i];
        const int hi = hybrid_idx[i];
        const int ni = numh_idx[i];
        const int xi = chiral_idx[i];
        const int4 bc = reinterpret_cast<const int4*>(bond_counts)[i];
        const float s0 = scalar3[3 * i + 0];
        const float s1 = scalar3[3 * i + 1];
        const float s2 = scalar3[3 * i + 2];

        const int r2 = (di * 5 + ni) * 3 + hi;
        const int r3 = ci * 4 + xi;
        const int rb0 = bc.x * 5 + bc.y;
        const int rb1 = bc.z * 5 + bc.w;

        // 5 independent LDS.128 for max MLP
        float4 v0 = s4[(OFF_T1 >> 2) + ai  * DV + lane];
        float4 v1 = s4[(OFF_T2 >> 2) + r2  * DV + lane];
        float4 v2 = s4[(OFF_T3 >> 2) + r3  * DV + lane];
        float4 v3 = s4[(OFF_B0 >> 2) + rb0 * DV + lane];
        float4 v4 = s4[(OFF_B1 >> 2) + rb1 * DV + lane];

        add4(v0, v1);
        add4(v2, v3);
        add4(v0, v4);
        add4(v0, v2);
        fma4(v0, s0, w0);
        fma4(v0, s1, w1);
        fma4(v0, s2, w2);

        out4[i * DV + lane] = v0;
    }
}

extern "C" void kernel_launch(void* const* d_in, const int* in_sizes, int n_in,
                              void* d_out, int out_size) {
    const int*   atom_idx    = (const int*)d_in[0];
    const int*   degree_idx  = (const int*)d_in[1];
    const int*   charge_idx  = (const int*)d_in[2];
    const int*   hybrid_idx  = (const int*)d_in[3];
    const int*   numh_idx    = (const int*)d_in[4];
    const int*   chiral_idx  = (const int*)d_in[5];
    const int*   bond_counts = (const int*)d_in[6];
    const float* scalar3     = (const float*)d_in[7];
    const float* E_atom      = (const float*)d_in[8];
    const float* E_deg       = (const float*)d_in[9];
    const float* E_chg       = (const float*)d_in[10];
    const float* E_hyb       = (const float*)d_in[11];
    const float* E_h         = (const float*)d_in[12];
    const float* E_chi       = (const float*)d_in[13];
    const float* E_bond      = (const float*)d_in[14];
    const float* Wm          = (const float*)d_in[15];
    const float* bv          = (const float*)d_in[16];
    float* out = (float*)d_out;

    const int n = in_sizes[0];

    static bool attr_set = false;   // attribute is sticky; setting it is idempotent
    if (!attr_set) {
        cudaFuncSetAttribute(atom_featurizer_kernel,
                             cudaFuncAttributeMaxDynamicSharedMemorySize, SMEM_BYTES);
        attr_set = true;
    }

    const int blocks = 152;   // 1 CTA/SM (smem-limited), persistent grid-stride
    atom_featurizer_kernel<<<blocks, NTHREADS, SMEM_BYTES>>>(
        atom_idx, degree_idx, charge_idx, hybrid_idx, numh_idx, chiral_idx,
        bond_counts, scalar3, E_atom, E_deg, E_chg, E_hyb, E_h, E_chi,
        E_bond, Wm, bv, out, n);
}

// round 3
// speedup vs baseline: 4.8379x; 4.8379x over previous
#include <cuda_runtime.h>
#include <cuda_bf16.h>

#define D 128
#define DV 32                 // float4 per embedding row
#define NTHREADS 256
#define TILE 512              // atoms per CTA tile
#define NBLOCKS 304           // 2 CTAs/SM x 152 SMs

// Combined tables (rows)
#define R_T1 46               // E_atom + bias
#define R_DH 18               // deg(6) x hyb(3)
#define R_HC 20               // numh(5) x chiral(4)
#define R_CG 11               // charge
#define R_B0 25               // (c0,c1): masked E_bond + c/4 * (W3,W4)
#define R_B1 25               // (c2,c3): masked E_bond + c/4 * (W5,W6)

#define OFF_T1 0
#define OFF_DH (OFF_T1 + R_T1 * D)
#define OFF_HC (OFF_DH + R_DH * D)
#define OFF_CG (OFF_HC + R_HC * D)
#define OFF_B0 (OFF_CG + R_CG * D)
#define OFF_B1 (OFF_B0 + R_B0 * D)
#define OFF_META (OFF_B1 + R_B1 * D)            // float4[TILE] = 2048 floats
#define SMEM_FLOATS (OFF_META + TILE * 4)       // 20608 floats
#define SMEM_BYTES  (SMEM_FLOATS * 4)           // 82432 B -> 2 CTAs/SM

__device__ __forceinline__ void add4(float4& a, const float4 b) {
    a.x += b.x; a.y += b.y; a.z += b.z; a.w += b.w;
}
__device__ __forceinline__ void fma4(float4& a, float s, const float4 b) {
    a.x = fmaf(s, b.x, a.x); a.y = fmaf(s, b.y, a.y);
    a.z = fmaf(s, b.z, a.z); a.w = fmaf(s, b.w, a.w);
}

// Coalesced per-atom metadata load -> packed float4 {s0, s1, s2, idxpack}
// idxpack bits: ai[0:6) rdh[6:11) rhc[11:16) ci[16:20) rb0[20:25) rb1[25:30)
__device__ __forceinline__ float4 load_meta_one(
    long a, long n,
    const int* __restrict__ atom_idx, const int* __restrict__ degree_idx,
    const int* __restrict__ charge_idx, const int* __restrict__ hybrid_idx,
    const int* __restrict__ numh_idx, const int* __restrict__ chiral_idx,
    const int* __restrict__ bond_counts, const float* __restrict__ scalar3)
{
    if (a >= n) return make_float4(0.f, 0.f, 0.f, 0.f);
    const int ai = atom_idx[a];
    const int di = degree_idx[a];
    const int ci = charge_idx[a];
    const int hi = hybrid_idx[a];
    const int ni = numh_idx[a];
    const int xi = chiral_idx[a];
    const int4 bc = reinterpret_cast<const int4*>(bond_counts)[a];
    unsigned p = (unsigned)ai
               | ((unsigned)(di * 3 + hi)     << 6)
               | ((unsigned)(ni * 4 + xi)     << 11)
               | ((unsigned)ci                << 16)
               | ((unsigned)(bc.x * 5 + bc.y) << 20)
               | ((unsigned)(bc.z * 5 + bc.w) << 25);
    return make_float4(scalar3[3 * a + 0], scalar3[3 * a + 1],
                       scalar3[3 * a + 2], __uint_as_float(p));
}

__global__ void __launch_bounds__(NTHREADS)
atom_featurizer_kernel(
    const int* __restrict__ atom_idx,
    const int* __restrict__ degree_idx,
    const int* __restrict__ charge_idx,
    const int* __restrict__ hybrid_idx,
    const int* __restrict__ numh_idx,
    const int* __restrict__ chiral_idx,
    const int* __restrict__ bond_counts,   // [N,4]
    const float* __restrict__ scalar3,     // [N,3]
    const float* __restrict__ E_atom,
    const float* __restrict__ E_deg,
    const float* __restrict__ E_chg,
    const float* __restrict__ E_hyb,
    const float* __restrict__ E_h,
    const float* __restrict__ E_chi,
    const float* __restrict__ E_bond,
    const float* __restrict__ Wm,
    const float* __restrict__ bv,
    float* __restrict__ out,
    long n)
{
    extern __shared__ float s[];
    const int t = threadIdx.x;

    // ---- Build combined tables (once per CTA) ----
    for (int e = t; e < R_T1 * D; e += NTHREADS)
        s[OFF_T1 + e] = E_atom[e] + bv[e & (D - 1)];
    for (int e = t; e < R_DH * D; e += NTHREADS) {
        int row = e >> 7, col = e & (D - 1);
        int di = row / 3, hi = row % 3;
        s[OFF_DH + e] = E_deg[di * D + col] + E_hyb[hi * D + col];
    }
    for (int e = t; e < R_HC * D; e += NTHREADS) {
        int row = e >> 7, col = e & (D - 1);
        int ni = row >> 2, xi = row & 3;
        s[OFF_HC + e] = E_h[ni * D + col] + E_chi[xi * D + col];
    }
    for (int e = t; e < R_CG * D; e += NTHREADS)
        s[OFF_CG + e] = E_chg[e];
    for (int e = t; e < R_B0 * D; e += NTHREADS) {
        int row = e >> 7, col = e & (D - 1);
        int c0 = row / 5, c1 = row % 5;
        float v = 0.25f * (c0 * Wm[3 * D + col] + c1 * Wm[4 * D + col]);
        if (c0 > 0) v += E_bond[c0 * D + col];
        if (c1 > 0) v += E_bond[c1 * D + col];
        s[OFF_B0 + e] = v;
    }
    for (int e = t; e < R_B1 * D; e += NTHREADS) {
        int row = e >> 7, col = e & (D - 1);
        int c2 = row / 5, c3 = row % 5;
        float v = 0.25f * (c2 * Wm[5 * D + col] + c3 * Wm[6 * D + col]);
        if (c2 > 0) v += E_bond[c2 * D + col];
        if (c3 > 0) v += E_bond[c3 * D + col];
        s[OFF_B1 + e] = v;
    }

    const int lane = t & 31;
    const int warp = t >> 5;

    // W rows 0..2 slices live in registers (lane-invariant)
    const float4* W4 = reinterpret_cast<const float4*>(Wm);
    const float4 w0 = W4[0 * DV + lane];
    const float4 w1 = W4[1 * DV + lane];
    const float4 w2 = W4[2 * DV + lane];

    const long NT = (n + TILE - 1) / TILE;
    long tile = blockIdx.x;

    // Prefetch tile 0 metadata into registers (coalesced)
    float4 pf0, pf1;
    if (tile < NT) {
        pf0 = load_meta_one(tile * TILE + t, n, atom_idx, degree_idx, charge_idx,
                            hybrid_idx, numh_idx, chiral_idx, bond_counts, scalar3);
        pf1 = load_meta_one(tile * TILE + NTHREADS + t, n, atom_idx, degree_idx, charge_idx,
                            hybrid_idx, numh_idx, chiral_idx, bond_counts, scalar3);
    }

    const float4* s4 = reinterpret_cast<const float4*>(s);
    float4* meta4 = reinterpret_cast<float4*>(s + OFF_META);
    float4* out4 = reinterpret_cast<float4*>(out);

    for (; tile < NT; tile += gridDim.x) {
        // Publish current tile metadata
        meta4[t] = pf0;
        meta4[NTHREADS + t] = pf1;
        __syncthreads();   // also covers table build on first iteration

        // Kick off next tile's metadata loads (latency hidden under compute)
        const long nxt = tile + gridDim.x;
        if (nxt < NT) {
            pf0 = load_meta_one(nxt * TILE + t, n, atom_idx, degree_idx, charge_idx,
                                hybrid_idx, numh_idx, chiral_idx, bond_counts, scalar3);
            pf1 = load_meta_one(nxt * TILE + NTHREADS + t, n, atom_idx, degree_idx, charge_idx,
                                hybrid_idx, numh_idx, chiral_idx, bond_counts, scalar3);
        }

        // Compute: each warp handles 64 contiguous atoms of this tile
        const long base = tile * TILE + warp * 64;
        #pragma unroll 4
        for (int k = 0; k < 64; k++) {
            const long g = base + k;
            if (g >= n) break;                    // warp-uniform
            const float4 m = meta4[warp * 64 + k]; // broadcast LDS.128
            const unsigned p = __float_as_uint(m.w);

            const int ai  =  p        & 63;
            const int rdh = (p >> 6)  & 31;
            const int rhc = (p >> 11) & 31;
            const int ci  = (p >> 16) & 15;
            const int rb0 = (p >> 20) & 31;
            const int rb1 = (p >> 25) & 31;

            float4 v0 = s4[(OFF_T1 >> 2) + ai  * DV + lane];
            float4 v1 = s4[(OFF_DH >> 2) + rdh * DV + lane];
            float4 v2 = s4[(OFF_HC >> 2) + rhc * DV + lane];
            float4 v3 = s4[(OFF_CG >> 2) + ci  * DV + lane];
            float4 v4 = s4[(OFF_B0 >> 2) + rb0 * DV + lane];
            float4 v5 = s4[(OFF_B1 >> 2) + rb1 * DV + lane];

            add4(v0, v1);
            add4(v2, v3);
            add4(v4, v5);
            add4(v0, v2);
            add4(v0, v4);
            fma4(v0, m.x, w0);
            fma4(v0, m.y, w1);
            fma4(v0, m.z, w2);

            out4[g * DV + lane] = v0;
        }
        __syncthreads();   // all warps done with meta before overwrite
    }
}

extern "C" void kernel_launch(void* const* d_in, const int* in_sizes, int n_in,
                              void* d_out, int out_size) {
    const int*   atom_idx    = (const int*)d_in[0];
    const int*   degree_idx  = (const int*)d_in[1];
    const int*   charge_idx  = (const int*)d_in[2];
    const int*   hybrid_idx  = (const int*)d_in[3];
    const int*   numh_idx    = (const int*)d_in[4];
    const int*   chiral_idx  = (const int*)d_in[5];
    const int*   bond_counts = (const int*)d_in[6];
    const float* scalar3     = (const float*)d_in[7];
    const float* E_atom      = (const float*)d_in[8];
    const float* E_deg       = (const float*)d_in[9];
    const float* E_chg       = (const float*)d_in[10];
    const float* E_hyb       = (const float*)d_in[11];
    const float* E_h         = (const float*)d_in[12];
    const float* E_chi       = (const float*)d_in[13];
    const float* E_bond      = (const float*)d_in[14];
    const float* Wm          = (const float*)d_in[15];
    const float* bv          = (const float*)d_in[16];
    float* out = (float*)d_out;

    const long n = in_sizes[0];

    static bool attr_set = false;
    if (!attr_set) {
        cudaFuncSetAttribute(atom_featurizer_kernel,
                             cudaFuncAttributeMaxDynamicSharedMemorySize, SMEM_BYTES);
        attr_set = true;
    }

    atom_featurizer_kernel<<<NBLOCKS, NTHREADS, SMEM_BYTES>>>(
        atom_idx, degree_idx, charge_idx, hybrid_idx, numh_idx, chiral_idx,
        bond_counts, scalar3, E_atom, E_deg, E_chg, E_hyb, E_h, E_chi,
        E_bond, Wm, bv, out, n);
}

// round 4
// speedup vs baseline: 5.7071x; 1.1797x over previous
#include <cuda_runtime.h>
#include <cuda_fp16.h>

#define D 128
#define NTHREADS 256
#define TILE 256              // atoms per CTA tile (meta float4 per atom = 4KB)
#define CTAS_PER_SM 3
#define NBLOCKS (152 * CTAS_PER_SM)

// Combined fp16 tables (rows of 128 halves = 256B)
#define R_T1 46               // E_atom + bias
#define R_DH 18               // deg(6) x hyb(3)
#define R_HC 20               // numh(5) x chiral(4)
#define R_CG 11               // charge
#define R_B0 25               // (c0,c1): masked E_bond + c/4*(W3,W4)
#define R_B1 25               // (c2,c3): masked E_bond + c/4*(W5,W6)
#define R_TOT (R_T1 + R_DH + R_HC + R_CG + R_B0 + R_B1)   // 145

// Row offsets (rows)
#define ROW_T1 0
#define ROW_DH (ROW_T1 + R_T1)   // 46
#define ROW_HC (ROW_DH + R_DH)   // 64
#define ROW_CG (ROW_HC + R_HC)   // 84
#define ROW_B0 (ROW_CG + R_CG)   // 95
#define ROW_B1 (ROW_B0 + R_B0)   // 120

#define TAB_BYTES (R_TOT * D * 2)          // 37120
#define META_OFF  TAB_BYTES
#define SMEM_BYTES (TAB_BYTES + TILE * 16) // 41216

__device__ __forceinline__ unsigned hadd2u(unsigned a, unsigned b) {
    __half2 r = __hadd2(*reinterpret_cast<__half2*>(&a),
                        *reinterpret_cast<__half2*>(&b));
    return *reinterpret_cast<unsigned*>(&r);
}
__device__ __forceinline__ uint4 hadd8(uint4 a, uint4 b) {
    uint4 r;
    r.x = hadd2u(a.x, b.x); r.y = hadd2u(a.y, b.y);
    r.z = hadd2u(a.z, b.z); r.w = hadd2u(a.w, b.w);
    return r;
}
__device__ __forceinline__ float lo2f(unsigned u) {
    return __low2float(*reinterpret_cast<__half2*>(&u));
}
__device__ __forceinline__ float hi2f(unsigned u) {
    return __high2float(*reinterpret_cast<__half2*>(&u));
}

// Coalesced per-atom metadata -> {s0, s1, s2, packed_indices}
// bits: ai[0:6) rdh[6:11) rhc[11:16) ci[16:20) rb0[20:25) rb1[25:30)
__device__ __forceinline__ float4 load_meta_one(
    long a, long n,
    const int* __restrict__ atom_idx, const int* __restrict__ degree_idx,
    const int* __restrict__ charge_idx, const int* __restrict__ hybrid_idx,
    const int* __restrict__ numh_idx, const int* __restrict__ chiral_idx,
    const int* __restrict__ bond_counts, const float* __restrict__ scalar3)
{
    if (a >= n) return make_float4(0.f, 0.f, 0.f, 0.f);
    const int ai = atom_idx[a];
    const int di = degree_idx[a];
    const int ci = charge_idx[a];
    const int hi = hybrid_idx[a];
    const int ni = numh_idx[a];
    const int xi = chiral_idx[a];
    const int4 bc = reinterpret_cast<const int4*>(bond_counts)[a];
    unsigned p = (unsigned)ai
               | ((unsigned)(di * 3 + hi)     << 6)
               | ((unsigned)(ni * 4 + xi)     << 11)
               | ((unsigned)ci                << 16)
               | ((unsigned)(bc.x * 5 + bc.y) << 20)
               | ((unsigned)(bc.z * 5 + bc.w) << 25);
    return make_float4(scalar3[3 * a + 0], scalar3[3 * a + 1],
                       scalar3[3 * a + 2], __uint_as_float(p));
}

__global__ void __launch_bounds__(NTHREADS, CTAS_PER_SM)
atom_featurizer_kernel(
    const int* __restrict__ atom_idx,
    const int* __restrict__ degree_idx,
    const int* __restrict__ charge_idx,
    const int* __restrict__ hybrid_idx,
    const int* __restrict__ numh_idx,
    const int* __restrict__ chiral_idx,
    const int* __restrict__ bond_counts,
    const float* __restrict__ scalar3,
    const float* __restrict__ E_atom,
    const float* __restrict__ E_deg,
    const float* __restrict__ E_chg,
    const float* __restrict__ E_hyb,
    const float* __restrict__ E_h,
    const float* __restrict__ E_chi,
    const float* __restrict__ E_bond,
    const float* __restrict__ Wm,
    const float* __restrict__ bv,
    float* __restrict__ out,
    long n)
{
    extern __shared__ __align__(16) char smem_raw[];
    __half* sh = reinterpret_cast<__half*>(smem_raw);
    float4* meta4 = reinterpret_cast<float4*>(smem_raw + META_OFF);

    const int t = threadIdx.x;

    // ---- Build combined fp16 tables (once per persistent CTA) ----
    for (int e = t; e < R_TOT * D; e += NTHREADS) {
        const int row = e >> 7, col = e & (D - 1);
        float v;
        if (row < ROW_DH) {                      // T1: atom + bias
            v = E_atom[row * D + col] + bv[col];
        } else if (row < ROW_HC) {               // DH: deg x hyb
            int r = row - ROW_DH;
            v = E_deg[(r / 3) * D + col] + E_hyb[(r % 3) * D + col];
        } else if (row < ROW_CG) {               // HC: numh x chiral
            int r = row - ROW_HC;
            v = E_h[(r >> 2) * D + col] + E_chi[(r & 3) * D + col];
        } else if (row < ROW_B0) {               // CG: charge
            v = E_chg[(row - ROW_CG) * D + col];
        } else if (row < ROW_B1) {               // B0: (c0,c1)
            int r = row - ROW_B0;
            int c0 = r / 5, c1 = r % 5;
            v = 0.25f * (c0 * Wm[3 * D + col] + c1 * Wm[4 * D + col]);
            if (c0 > 0) v += E_bond[c0 * D + col];
            if (c1 > 0) v += E_bond[c1 * D + col];
        } else {                                 // B1: (c2,c3)
            int r = row - ROW_B1;
            int c2 = r / 5, c3 = r % 5;
            v = 0.25f * (c2 * Wm[5 * D + col] + c3 * Wm[6 * D + col]);
            if (c2 > 0) v += E_bond[c2 * D + col];
            if (c3 > 0) v += E_bond[c3 * D + col];
        }
        sh[e] = __float2half_rn(v);
    }

    const int lane = t & 31;
    const int warp = t >> 5;
    const int j = lane & 15;       // 16B chunk within row (owns dims [8j, 8j+8))
    const int sub = lane >> 4;     // 0 -> atom A, 1 -> atom B

    // W rows 0..2 slices for this lane's 8 dims -> registers (fp32, exact)
    const float4 w0a = *reinterpret_cast<const float4*>(Wm + 0 * D + j * 8);
    const float4 w0b = *reinterpret_cast<const float4*>(Wm + 0 * D + j * 8 + 4);
    const float4 w1a = *reinterpret_cast<const float4*>(Wm + 1 * D + j * 8);
    const float4 w1b = *reinterpret_cast<const float4*>(Wm + 1 * D + j * 8 + 4);
    const float4 w2a = *reinterpret_cast<const float4*>(Wm + 2 * D + j * 8);
    const float4 w2b = *reinterpret_cast<const float4*>(Wm + 2 * D + j * 8 + 4);

    const uint4* tab = reinterpret_cast<const uint4*>(sh);  // 16 uint4 per row
    float4* out4 = reinterpret_cast<float4*>(out);

    const long NT = (n + TILE - 1) / TILE;
    long tile = blockIdx.x;

    // Prefetch tile 0 metadata (coalesced; one atom per thread)
    float4 pf;
    if (tile < NT)
        pf = load_meta_one(tile * TILE + t, n, atom_idx, degree_idx, charge_idx,
                           hybrid_idx, numh_idx, chiral_idx, bond_counts, scalar3);

    for (; tile < NT; tile += gridDim.x) {
        meta4[t] = pf;
        __syncthreads();     // covers table build on first iteration too

        const long nxt = tile + gridDim.x;
        if (nxt < NT)
            pf = load_meta_one(nxt * TILE + t, n, atom_idx, degree_idx, charge_idx,
                               hybrid_idx, numh_idx, chiral_idx, bond_counts, scalar3);

        // Each warp: 32 contiguous atoms of this tile, 2 per iteration
        const int abase = warp * 32;
        const long gbase = tile * TILE + abase;

        #pragma unroll 2
        for (int k = 0; k < 16; k++) {
            const int a = abase + 2 * k + sub;          // atom-in-tile (per half-warp)
            const long g = tile * (long)TILE + a;       // global atom
            const float4 m = meta4[a];                  // half-warp broadcast
            const unsigned p = __float_as_uint(m.w);

            const int i1 = ( p        & 63) + ROW_T1 * 0;
            const int i2 = ((p >> 6)  & 31) + ROW_DH;
            const int i3 = ((p >> 11) & 31) + ROW_HC;
            const int i4 = ((p >> 16) & 15) + ROW_CG;
            const int i5 = ((p >> 20) & 31) + ROW_B0;
            const int i6 = ((p >> 25) & 31) + ROW_B1;

            // 6 LDS.128 (each: 2 rows across the warp, conflict-free)
            const uint4 t1 = tab[i1 * 16 + j];
            const uint4 dh = tab[i2 * 16 + j];
            const uint4 hc = tab[i3 * 16 + j];
            const uint4 cg = tab[i4 * 16 + j];
            const uint4 b0 = tab[i5 * 16 + j];
            const uint4 b1 = tab[i6 * 16 + j];

            // half2 subtrees, then fp32 combine
            const uint4 sA = hadd8(hadd8(t1, dh), hadd8(hc, cg));
            const uint4 sB = hadd8(b0, b1);

            float4 olo, ohi;
            olo.x = lo2f(sA.x) + lo2f(sB.x);
            olo.y = hi2f(sA.x) + hi2f(sB.x);
            olo.z = lo2f(sA.y) + lo2f(sB.y);
            olo.w = hi2f(sA.y) + hi2f(sB.y);
            ohi.x = lo2f(sA.z) + lo2f(sB.z);
            ohi.y = hi2f(sA.z) + hi2f(sB.z);
            ohi.z = lo2f(sA.w) + lo2f(sB.w);
            ohi.w = hi2f(sA.w) + hi2f(sB.w);

            olo.x = fmaf(m.x, w0a.x, olo.x); olo.y = fmaf(m.x, w0a.y, olo.y);
            olo.z = fmaf(m.x, w0a.z, olo.z); olo.w = fmaf(m.x, w0a.w, olo.w);
            ohi.x = fmaf(m.x, w0b.x, ohi.x); ohi.y = fmaf(m.x, w0b.y, ohi.y);
            ohi.z = fmaf(m.x, w0b.z, ohi.z); ohi.w = fmaf(m.x, w0b.w, ohi.w);

            olo.x = fmaf(m.y, w1a.x, olo.x); olo.y = fmaf(m.y, w1a.y, olo.y);
            olo.z = fmaf(m.y, w1a.z, olo.z); olo.w = fmaf(m.y, w1a.w, olo.w);
            ohi.x = fmaf(m.y, w1b.x, ohi.x); ohi.y = fmaf(m.y, w1b.y, ohi.y);
            ohi.z = fmaf(m.y, w1b.z, ohi.z); ohi.w = fmaf(m.y, w1b.w, ohi.w);

            olo.x = fmaf(m.z, w2a.x, olo.x); olo.y = fmaf(m.z, w2a.y, olo.y);
            olo.z = fmaf(m.z, w2a.z, olo.z); olo.w = fmaf(m.z, w2a.w, olo.w);
            ohi.x = fmaf(m.z, w2b.x, ohi.x); ohi.y = fmaf(m.z, w2b.y, ohi.y);
            ohi.z = fmaf(m.z, w2b.z, ohi.z); ohi.w = fmaf(m.z, w2b.w, ohi.w);

            if (g < n) {
                out4[g * 32 + j * 2]     = olo;
                out4[g * 32 + j * 2 + 1] = ohi;
            }
        }
        __syncthreads();   // meta consumed before next publish
    }
}

extern "C" void kernel_launch(void* const* d_in, const int* in_sizes, int n_in,
                              void* d_out, int out_size) {
    const int*   atom_idx    = (const int*)d_in[0];
    const int*   degree_idx  = (const int*)d_in[1];
    const int*   charge_idx  = (const int*)d_in[2];
    const int*   hybrid_idx  = (const int*)d_in[3];
    const int*   numh_idx    = (const int*)d_in[4];
    const int*   chiral_idx  = (const int*)d_in[5];
    const int*   bond_counts = (const int*)d_in[6];
    const float* scalar3     = (const float*)d_in[7];
    const float* E_atom      = (const float*)d_in[8];
    const float* E_deg       = (const float*)d_in[9];
    const float* E_chg       = (const float*)d_in[10];
    const float* E_hyb       = (const float*)d_in[11];
    const float* E_h         = (const float*)d_in[12];
    const float* E_chi       = (const float*)d_in[13];
    const float* E_bond      = (const float*)d_in[14];
    const float* Wm          = (const float*)d_in[15];
    const float* bv          = (const float*)d_in[16];
    float* out = (float*)d_out;

    const long n = in_sizes[0];

    static bool attr_set = false;
    if (!attr_set) {
        cudaFuncSetAttribute(atom_featurizer_kernel,
                             cudaFuncAttributeMaxDynamicSharedMemorySize, SMEM_BYTES);
        attr_set = true;
    }

    atom_featurizer_kernel<<<NBLOCKS, NTHREADS, SMEM_BYTES>>>(
        atom_idx, degree_idx, charge_idx, hybrid_idx, numh_idx, chiral_idx,
        bond_counts, scalar3, E_atom, E_deg, E_chg, E_hyb, E_h, E_chi,
        E_bond, Wm, bv, out, n);
}

// round 5
// speedup vs baseline: 5.8408x; 1.0234x over previous
#include <cuda_runtime.h>
#include <cuda_fp16.h>

#define D 128
#define NTHREADS 256
#define TILE 256
#define CTAS_PER_SM 4
#define NBLOCKS (152 * CTAS_PER_SM)

// Combined fp16 tables (rows of 128 halves = 256B)
#define R_T1 46
#define R_DH 18
#define R_HC 20
#define R_CG 11
#define R_B0 25
#define R_B1 25
#define R_TOT (R_T1 + R_DH + R_HC + R_CG + R_B0 + R_B1)   // 145

#define ROW_T1 0
#define ROW_DH (ROW_T1 + R_T1)   // 46
#define ROW_HC (ROW_DH + R_DH)   // 64
#define ROW_CG (ROW_HC + R_HC)   // 84
#define ROW_B0 (ROW_CG + R_CG)   // 95
#define ROW_B1 (ROW_B0 + R_B0)   // 120

#define TAB_BYTES (R_TOT * D * 2)          // 37120
#define META_OFF  TAB_BYTES
#define SMEM_BYTES (TAB_BYTES + TILE * 16) // 41216

__device__ __forceinline__ unsigned hadd2u(unsigned a, unsigned b) {
    __half2 r = __hadd2(*reinterpret_cast<__half2*>(&a),
                        *reinterpret_cast<__half2*>(&b));
    return *reinterpret_cast<unsigned*>(&r);
}
__device__ __forceinline__ uint4 hadd8(uint4 a, uint4 b) {
    uint4 r;
    r.x = hadd2u(a.x, b.x); r.y = hadd2u(a.y, b.y);
    r.z = hadd2u(a.z, b.z); r.w = hadd2u(a.w, b.w);
    return r;
}
__device__ __forceinline__ float lo2f(unsigned u) {
    return __low2float(*reinterpret_cast<__half2*>(&u));
}
__device__ __forceinline__ float hi2f(unsigned u) {
    return __high2float(*reinterpret_cast<__half2*>(&u));
}

// Coalesced per-atom metadata -> {s0, s1, s2, packed_indices}
// bits: ai[0:6) rdh[6:11) rhc[11:16) ci[16:20) rb0[20:25) rb1[25:30)
__device__ __forceinline__ float4 load_meta_one(
    long a, long n,
    const int* __restrict__ atom_idx, const int* __restrict__ degree_idx,
    const int* __restrict__ charge_idx, const int* __restrict__ hybrid_idx,
    const int* __restrict__ numh_idx, const int* __restrict__ chiral_idx,
    const int* __restrict__ bond_counts, const float* __restrict__ scalar3)
{
    if (a >= n) return make_float4(0.f, 0.f, 0.f, 0.f);
    const int ai = __ldcs(atom_idx + a);
    const int di = __ldcs(degree_idx + a);
    const int ci = __ldcs(charge_idx + a);
    const int hi = __ldcs(hybrid_idx + a);
    const int ni = __ldcs(numh_idx + a);
    const int xi = __ldcs(chiral_idx + a);
    const int4 bc = __ldcs(reinterpret_cast<const int4*>(bond_counts) + a);
    unsigned p = (unsigned)ai
               | ((unsigned)(di * 3 + hi)     << 6)
               | ((unsigned)(ni * 4 + xi)     << 11)
               | ((unsigned)ci                << 16)
               | ((unsigned)(bc.x * 5 + bc.y) << 20)
               | ((unsigned)(bc.z * 5 + bc.w) << 25);
    return make_float4(__ldcs(scalar3 + 3 * a + 0), __ldcs(scalar3 + 3 * a + 1),
                       __ldcs(scalar3 + 3 * a + 2), __uint_as_float(p));
}

__global__ void __launch_bounds__(NTHREADS, CTAS_PER_SM)
atom_featurizer_kernel(
    const int* __restrict__ atom_idx,
    const int* __restrict__ degree_idx,
    const int* __restrict__ charge_idx,
    const int* __restrict__ hybrid_idx,
    const int* __restrict__ numh_idx,
    const int* __restrict__ chiral_idx,
    const int* __restrict__ bond_counts,
    const float* __restrict__ scalar3,
    const float* __restrict__ E_atom,
    const float* __restrict__ E_deg,
    const float* __restrict__ E_chg,
    const float* __restrict__ E_hyb,
    const float* __restrict__ E_h,
    const float* __restrict__ E_chi,
    const float* __restrict__ E_bond,
    const float* __restrict__ Wm,
    const float* __restrict__ bv,
    float* __restrict__ out,
    long n)
{
    extern __shared__ __align__(16) char smem_raw[];
    __half* sh = reinterpret_cast<__half*>(smem_raw);
    float4* meta4 = reinterpret_cast<float4*>(smem_raw + META_OFF);

    const int t = threadIdx.x;

    // ---- Build combined fp16 tables (once per persistent CTA) ----
    for (int e = t; e < R_TOT * D; e += NTHREADS) {
        const int row = e >> 7, col = e & (D - 1);
        float v;
        if (row < ROW_DH) {
            v = E_atom[row * D + col] + bv[col];
        } else if (row < ROW_CG) {
            if (row < ROW_HC) {
                int r = row - ROW_DH;
                v = E_deg[(r / 3) * D + col] + E_hyb[(r % 3) * D + col];
            } else {
                int r = row - ROW_HC;
                v = E_h[(r >> 2) * D + col] + E_chi[(r & 3) * D + col];
            }
        } else if (row < ROW_B0) {
            v = E_chg[(row - ROW_CG) * D + col];
        } else if (row < ROW_B1) {
            int r = row - ROW_B0;
            int c0 = r / 5, c1 = r % 5;
            v = 0.25f * (c0 * Wm[3 * D + col] + c1 * Wm[4 * D + col]);
            if (c0 > 0) v += E_bond[c0 * D + col];
            if (c1 > 0) v += E_bond[c1 * D + col];
        } else {
            int r = row - ROW_B1;
            int c2 = r / 5, c3 = r % 5;
            v = 0.25f * (c2 * Wm[5 * D + col] + c3 * Wm[6 * D + col]);
            if (c2 > 0) v += E_bond[c2 * D + col];
            if (c3 > 0) v += E_bond[c3 * D + col];
        }
        sh[e] = __float2half_rn(v);
    }

    const int lane = t & 31;
    const int warp = t >> 5;
    const int j = lane & 15;       // 16B chunk within row (dims [8j, 8j+8))
    const int sub = lane >> 4;     // 0 -> even atom, 1 -> odd atom

    // W rows 0..2 slices as half2 registers (12 regs instead of 24)
    __half2 w0h[4], w1h[4], w2h[4];
    #pragma unroll
    for (int q = 0; q < 4; q++) {
        w0h[q] = __floats2half2_rn(Wm[0 * D + j * 8 + 2 * q],
                                   Wm[0 * D + j * 8 + 2 * q + 1]);
        w1h[q] = __floats2half2_rn(Wm[1 * D + j * 8 + 2 * q],
                                   Wm[1 * D + j * 8 + 2 * q + 1]);
        w2h[q] = __floats2half2_rn(Wm[2 * D + j * 8 + 2 * q],
                                   Wm[2 * D + j * 8 + 2 * q + 1]);
    }

    const uint4* tab = reinterpret_cast<const uint4*>(sh);  // 16 uint4 per row
    float4* out4 = reinterpret_cast<float4*>(out);

    const long NT = (n + TILE - 1) / TILE;
    long tile = blockIdx.x;

    float4 pf;
    if (tile < NT)
        pf = load_meta_one(tile * TILE + t, n, atom_idx, degree_idx, charge_idx,
                           hybrid_idx, numh_idx, chiral_idx, bond_counts, scalar3);

    for (; tile < NT; tile += gridDim.x) {
        meta4[t] = pf;
        __syncthreads();

        const long nxt = tile + gridDim.x;
        if (nxt < NT)
            pf = load_meta_one(nxt * TILE + t, n, atom_idx, degree_idx, charge_idx,
                               hybrid_idx, numh_idx, chiral_idx, bond_counts, scalar3);

        const int abase = warp * 32;

        #pragma unroll 2
        for (int k = 0; k < 16; k++) {
            const int a = abase + 2 * k + sub;
            const long g = tile * (long)TILE + a;
            const float4 m = meta4[a];
            const unsigned p = __float_as_uint(m.w);

            const int i1 =  p        & 63;
            const int i2 = ((p >> 6)  & 31) + ROW_DH;
            const int i3 = ((p >> 11) & 31) + ROW_HC;
            const int i4 = ((p >> 16) & 15) + ROW_CG;
            const int i5 = ((p >> 20) & 31) + ROW_B0;
            const int i6 = ((p >> 25) & 31) + ROW_B1;

            const uint4 t1 = tab[i1 * 16 + j];
            const uint4 dh = tab[i2 * 16 + j];
            const uint4 hc = tab[i3 * 16 + j];
            const uint4 cg = tab[i4 * 16 + j];
            const uint4 b0 = tab[i5 * 16 + j];
            const uint4 b1 = tab[i6 * 16 + j];

            // Subtree A: four categorical lookups in half2
            const uint4 sA = hadd8(hadd8(t1, dh), hadd8(hc, cg));
            // Subtree B: bond tables + s.W (all small-magnitude) in half2
            uint4 sB = hadd8(b0, b1);
            {
                const __half2 s0h = __float2half2_rn(m.x);
                const __half2 s1h = __float2half2_rn(m.y);
                const __half2 s2h = __float2half2_rn(m.z);
                unsigned* sw = &sB.x;
                #pragma unroll
                for (int q = 0; q < 4; q++) {
                    __half2 acc = __hmul2(s0h, w0h[q]);
                    acc = __hfma2(s1h, w1h[q], acc);
                    acc = __hfma2(s2h, w2h[q], acc);
                    sw[q] = hadd2u(sw[q], *reinterpret_cast<unsigned*>(&acc));
                }
            }

            // fp32 combine (one add per element)
            float4 olo, ohi;
            olo.x = lo2f(sA.x) + lo2f(sB.x);
            olo.y = hi2f(sA.x) + hi2f(sB.x);
            olo.z = lo2f(sA.y) + lo2f(sB.y);
            olo.w = hi2f(sA.y) + hi2f(sB.y);
            ohi.x = lo2f(sA.z) + lo2f(sB.z);
            ohi.y = hi2f(sA.z) + hi2f(sB.z);
            ohi.z = lo2f(sA.w) + lo2f(sB.w);
            ohi.w = hi2f(sA.w) + hi2f(sB.w);

            if (g < n) {
                __stcs(&out4[g * 32 + j * 2],     olo);
                __stcs(&out4[g * 32 + j * 2 + 1], ohi);
            }
        }
        __syncthreads();
    }
}

extern "C" void kernel_launch(void* const* d_in, const int* in_sizes, int n_in,
                              void* d_out, int out_size) {
    const int*   atom_idx    = (const int*)d_in[0];
    const int*   degree_idx  = (const int*)d_in[1];
    const int*   charge_idx  = (const int*)d_in[2];
    const int*   hybrid_idx  = (const int*)d_in[3];
    const int*   numh_idx    = (const int*)d_in[4];
    const int*   chiral_idx  = (const int*)d_in[5];
    const int*   bond_counts = (const int*)d_in[6];
    const float* scalar3     = (const float*)d_in[7];
    const float* E_atom      = (const float*)d_in[8];
    const float* E_deg       = (const float*)d_in[9];
    const float* E_chg       = (const float*)d_in[10];
    const float* E_hyb       = (const float*)d_in[11];
    const float* E_h         = (const float*)d_in[12];
    const float* E_chi       = (const float*)d_in[13];
    const float* E_bond      = (const float*)d_in[14];
    const float* Wm          = (const float*)d_in[15];
    const float* bv          = (const float*)d_in[16];
    float* out = (float*)d_out;

    const long n = in_sizes[0];

    static bool attr_set = false;
    if (!attr_set) {
        cudaFuncSetAttribute(atom_featurizer_kernel,
                             cudaFuncAttributeMaxDynamicSharedMemorySize, SMEM_BYTES);
        attr_set = true;
    }

    atom_featurizer_kernel<<<NBLOCKS, NTHREADS, SMEM_BYTES>>>(
        atom_idx, degree_idx, charge_idx, hybrid_idx, numh_idx, chiral_idx,
        bond_counts, scalar3, E_atom, E_deg, E_chg, E_hyb, E_h, E_chi,
        E_bond, Wm, bv, out, n);
}

// round 6
// speedup vs baseline: 6.4014x; 1.0960x over previous
#include <cuda_runtime.h>
#include <cuda_fp16.h>

#define D 128
#define NTHREADS 256
#define CTAS_PER_SM 4
#define NBLOCKS (152 * CTAS_PER_SM)

// Combined fp16 tables (rows of 128 halves = 256B)
#define R_T1 46
#define R_DH 18
#define R_HC 20
#define R_CG 11
#define R_B0 25
#define R_B1 25
#define R_TOT (R_T1 + R_DH + R_HC + R_CG + R_B0 + R_B1)   // 145

#define ROW_T1 0
#define ROW_DH (ROW_T1 + R_T1)   // 46
#define ROW_HC (ROW_DH + R_DH)   // 64
#define ROW_CG (ROW_HC + R_HC)   // 84
#define ROW_B0 (ROW_CG + R_CG)   // 95
#define ROW_B1 (ROW_B0 + R_B0)   // 120

#define SMEM_BYTES (R_TOT * D * 2)         // 37120 -> 4+ CTAs/SM

__device__ __forceinline__ unsigned hadd2u(unsigned a, unsigned b) {
    __half2 r = __hadd2(*reinterpret_cast<__half2*>(&a),
                        *reinterpret_cast<__half2*>(&b));
    return *reinterpret_cast<unsigned*>(&r);
}
__device__ __forceinline__ uint4 hadd8(uint4 a, uint4 b) {
    uint4 r;
    r.x = hadd2u(a.x, b.x); r.y = hadd2u(a.y, b.y);
    r.z = hadd2u(a.z, b.z); r.w = hadd2u(a.w, b.w);
    return r;
}
__device__ __forceinline__ float lo2f(unsigned u) {
    return __low2float(*reinterpret_cast<__half2*>(&u));
}
__device__ __forceinline__ float hi2f(unsigned u) {
    return __high2float(*reinterpret_cast<__half2*>(&u));
}

// Per-lane coalesced metadata load for one atom.
// pack bits: ai[0:6) rdh[6:11) rhc[11:16) ci[16:20) rb0[20:25) rb1[25:30)
__device__ __forceinline__ void load_meta_lane(
    long a, long n, float& s0, float& s1, float& s2, unsigned& p,
    const int* __restrict__ atom_idx, const int* __restrict__ degree_idx,
    const int* __restrict__ charge_idx, const int* __restrict__ hybrid_idx,
    const int* __restrict__ numh_idx, const int* __restrict__ chiral_idx,
    const int* __restrict__ bond_counts, const float* __restrict__ scalar3)
{
    if (a < n) {
        const int ai = __ldcs(atom_idx + a);
        const int di = __ldcs(degree_idx + a);
        const int ci = __ldcs(charge_idx + a);
        const int hi = __ldcs(hybrid_idx + a);
        const int ni = __ldcs(numh_idx + a);
        const int xi = __ldcs(chiral_idx + a);
        const int4 bc = __ldcs(reinterpret_cast<const int4*>(bond_counts) + a);
        p = (unsigned)ai
          | ((unsigned)(di * 3 + hi)     << 6)
          | ((unsigned)(ni * 4 + xi)     << 11)
          | ((unsigned)ci                << 16)
          | ((unsigned)(bc.x * 5 + bc.y) << 20)
          | ((unsigned)(bc.z * 5 + bc.w) << 25);
        s0 = __ldcs(scalar3 + 3 * a + 0);
        s1 = __ldcs(scalar3 + 3 * a + 1);
        s2 = __ldcs(scalar3 + 3 * a + 2);
    } else {
        p = 0u; s0 = 0.f; s1 = 0.f; s2 = 0.f;
    }
}

__global__ void __launch_bounds__(NTHREADS, CTAS_PER_SM)
atom_featurizer_kernel(
    const int* __restrict__ atom_idx,
    const int* __restrict__ degree_idx,
    const int* __restrict__ charge_idx,
    const int* __restrict__ hybrid_idx,
    const int* __restrict__ numh_idx,
    const int* __restrict__ chiral_idx,
    const int* __restrict__ bond_counts,
    const float* __restrict__ scalar3,
    const float* __restrict__ E_atom,
    const float* __restrict__ E_deg,
    const float* __restrict__ E_chg,
    const float* __restrict__ E_hyb,
    const float* __restrict__ E_h,
    const float* __restrict__ E_chi,
    const float* __restrict__ E_bond,
    const float* __restrict__ Wm,
    const float* __restrict__ bv,
    float* __restrict__ out,
    long n)
{
    extern __shared__ __align__(16) char smem_raw[];
    __half* sh = reinterpret_cast<__half*>(smem_raw);

    const int t = threadIdx.x;

    // ---- Build combined fp16 tables (once per persistent CTA) ----
    for (int e = t; e < R_TOT * D; e += NTHREADS) {
        const int row = e >> 7, col = e & (D - 1);
        float v;
        if (row < ROW_DH) {
            v = E_atom[row * D + col] + bv[col];
        } else if (row < ROW_CG) {
            if (row < ROW_HC) {
                int r = row - ROW_DH;
                v = E_deg[(r / 3) * D + col] + E_hyb[(r % 3) * D + col];
            } else {
                int r = row - ROW_HC;
                v = E_h[(r >> 2) * D + col] + E_chi[(r & 3) * D + col];
            }
        } else if (row < ROW_B0) {
            v = E_chg[(row - ROW_CG) * D + col];
        } else if (row < ROW_B1) {
            int r = row - ROW_B0;
            int c0 = r / 5, c1 = r % 5;
            v = 0.25f * (c0 * Wm[3 * D + col] + c1 * Wm[4 * D + col]);
            if (c0 > 0) v += E_bond[c0 * D + col];
            if (c1 > 0) v += E_bond[c1 * D + col];
        } else {
            int r = row - ROW_B1;
            int c2 = r / 5, c3 = r % 5;
            v = 0.25f * (c2 * Wm[5 * D + col] + c3 * Wm[6 * D + col]);
            if (c2 > 0) v += E_bond[c2 * D + col];
            if (c3 > 0) v += E_bond[c3 * D + col];
        }
        sh[e] = __float2half_rn(v);
    }

    const int lane = t & 31;
    const int warp = t >> 5;
    const int j = lane & 15;       // 16B chunk within row (dims [8j, 8j+8))
    const int sub = lane >> 4;     // 0 -> even atom, 1 -> odd atom

    // W rows 0..2 slices as half2 registers
    __half2 w0h[4], w1h[4], w2h[4];
    #pragma unroll
    for (int q = 0; q < 4; q++) {
        w0h[q] = __floats2half2_rn(Wm[0 * D + j * 8 + 2 * q],
                                   Wm[0 * D + j * 8 + 2 * q + 1]);
        w1h[q] = __floats2half2_rn(Wm[1 * D + j * 8 + 2 * q],
                                   Wm[1 * D + j * 8 + 2 * q + 1]);
        w2h[q] = __floats2half2_rn(Wm[2 * D + j * 8 + 2 * q],
                                   Wm[2 * D + j * 8 + 2 * q + 1]);
    }

    __syncthreads();   // tables ready; no barriers after this point

    const uint4* tab = reinterpret_cast<const uint4*>(sh);  // 16 uint4 per row
    float4* out4 = reinterpret_cast<float4*>(out);

    // Persistent warps, chunks of 32 atoms
    const long nchunks = (n + 31) >> 5;
    const long nwarps = (long)gridDim.x * (NTHREADS / 32);
    long chunk = (long)blockIdx.x * (NTHREADS / 32) + warp;

    // Prefetch chunk 0 metadata (one atom per lane, coalesced)
    float cs0, cs1, cs2; unsigned cp;
    if (chunk < nchunks)
        load_meta_lane(chunk * 32 + lane, n, cs0, cs1, cs2, cp,
                       atom_idx, degree_idx, charge_idx, hybrid_idx,
                       numh_idx, chiral_idx, bond_counts, scalar3);

    for (; chunk < nchunks; chunk += nwarps) {
        // Issue next chunk's loads now; they complete under this chunk's compute
        float ns0, ns1, ns2; unsigned np;
        const long nxt = chunk + nwarps;
        if (nxt < nchunks)
            load_meta_lane(nxt * 32 + lane, n, ns0, ns1, ns2, np,
                           atom_idx, degree_idx, charge_idx, hybrid_idx,
                           numh_idx, chiral_idx, bond_counts, scalar3);

        const long gbase = chunk * 32;

        #pragma unroll 4
        for (int k = 0; k < 16; k++) {
            const int src = 2 * k + sub;           // atom-in-chunk for this half-warp
            const long g = gbase + src;

            const float    m0 = __shfl_sync(0xffffffffu, cs0, src);
            const float    m1 = __shfl_sync(0xffffffffu, cs1, src);
            const float    m2 = __shfl_sync(0xffffffffu, cs2, src);
            const unsigned p  = __shfl_sync(0xffffffffu, cp,  src);

            const int i1 =  p        & 63;
            const int i2 = ((p >> 6)  & 31) + ROW_DH;
            const int i3 = ((p >> 11) & 31) + ROW_HC;
            const int i4 = ((p >> 16) & 15) + ROW_CG;
            const int i5 = ((p >> 20) & 31) + ROW_B0;
            const int i6 = ((p >> 25) & 31) + ROW_B1;

            const uint4 t1 = tab[i1 * 16 + j];
            const uint4 dh = tab[i2 * 16 + j];
            const uint4 hc = tab[i3 * 16 + j];
            const uint4 cg = tab[i4 * 16 + j];
            const uint4 b0 = tab[i5 * 16 + j];
            const uint4 b1 = tab[i6 * 16 + j];

            // Subtree A: categorical lookups
            const uint4 sA = hadd8(hadd8(t1, dh), hadd8(hc, cg));
            // Subtree B: bond tables + s.W in half2
            uint4 sB = hadd8(b0, b1);
            {
                const __half2 s0h = __float2half2_rn(m0);
                const __half2 s1h = __float2half2_rn(m1);
                const __half2 s2h = __float2half2_rn(m2);
                unsigned* sw = &sB.x;
                #pragma unroll
                for (int q = 0; q < 4; q++) {
                    __half2 acc = __hmul2(s0h, w0h[q]);
                    acc = __hfma2(s1h, w1h[q], acc);
                    acc = __hfma2(s2h, w2h[q], acc);
                    sw[q] = hadd2u(sw[q], *reinterpret_cast<unsigned*>(&acc));
                }
            }

            // fp32 combine
            float4 olo, ohi;
            olo.x = lo2f(sA.x) + lo2f(sB.x);
            olo.y = hi2f(sA.x) + hi2f(sB.x);
            olo.z = lo2f(sA.y) + lo2f(sB.y);
            olo.w = hi2f(sA.y) + hi2f(sB.y);
            ohi.x = lo2f(sA.z) + lo2f(sB.z);
            ohi.y = hi2f(sA.z) + hi2f(sB.z);
            ohi.z = lo2f(sA.w) + lo2f(sB.w);
            ohi.w = hi2f(sA.w) + hi2f(sB.w);

            if (g < n) {
                __stcs(&out4[g * 32 + j * 2],     olo);
                __stcs(&out4[g * 32 + j * 2 + 1], ohi);
            }
        }

        cs0 = ns0; cs1 = ns1; cs2 = ns2; cp = np;
    }
}

extern "C" void kernel_launch(void* const* d_in, const int* in_sizes, int n_in,
                              void* d_out, int out_size) {
    const int*   atom_idx    = (const int*)d_in[0];
    const int*   degree_idx  = (const int*)d_in[1];
    const int*   charge_idx  = (const int*)d_in[2];
    const int*   hybrid_idx  = (const int*)d_in[3];
    const int*   numh_idx    = (const int*)d_in[4];
    const int*   chiral_idx  = (const int*)d_in[5];
    const int*   bond_counts = (const int*)d_in[6];
    const float* scalar3     = (const float*)d_in[7];
    const float* E_atom      = (const float*)d_in[8];
    const float* E_deg       = (const float*)d_in[9];
    const float* E_chg       = (const float*)d_in[10];
    const float* E_hyb       = (const float*)d_in[11];
    const float* E_h         = (const float*)d_in[12];
    const float* E_chi       = (const float*)d_in[13];
    const float* E_bond      = (const float*)d_in[14];
    const float* Wm          = (const float*)d_in[15];
    const float* bv          = (const float*)d_in[16];
    float* out = (float*)d_out;

    const long n = in_sizes[0];

    static bool attr_set = false;
    if (!attr_set) {
        cudaFuncSetAttribute(atom_featurizer_kernel,
                             cudaFuncAttributeMaxDynamicSharedMemorySize, SMEM_BYTES);
        attr_set = true;
    }

    atom_featurizer_kernel<<<NBLOCKS, NTHREADS, SMEM_BYTES>>>(
        atom_idx, degree_idx, charge_idx, hybrid_idx, numh_idx, chiral_idx,
        bond_counts, scalar3, E_atom, E_deg, E_chg, E_hyb, E_h, E_chi,
        E_bond, Wm, bv, out, n);
}